// round 15
// baseline (speedup 1.0000x reference)
#include <cuda_runtime.h>
#include <float.h>

#define BB 4
#define NN 2048
#define MM 2048
#define DIN 3
#define HH 256
#define DD 64
#define KV 32
#define SPLITS 32
#define NSPLIT (NN / SPLITS)   /* 64 keys per split */
#define TK 16                  /* keys per shared tile */
#define QBLK 128               /* threads / queries per block */
#define BM (BB * MM)           /* 8192 queries total */
#define NCOMP (2 + KV)         /* 34 partial components: mval, ssum, acc[32] */
#define JCHUNK 128             /* W2 rows staged per chunk */

typedef unsigned long long u64;
#define NLOG2E_HALF (-0.7213475204444817f)   /* -0.5 * log2(e) */

__device__ __forceinline__ u64 mul2_(u64 a, u64 b) {
    u64 r; asm("mul.rn.f32x2 %0,%1,%2;" : "=l"(r) : "l"(a), "l"(b)); return r;
}
__device__ __forceinline__ u64 fma2_(u64 a, u64 b, u64 c) {
    u64 r; asm("fma.rn.f32x2 %0,%1,%2,%3;" : "=l"(r) : "l"(a), "l"(b), "l"(c)); return r;
}
__device__ __forceinline__ float ex2_(float x) {
    float r; asm("ex2.approx.f32 %0,%1;" : "=f"(r) : "f"(x)); return r;
}
__device__ __forceinline__ u64 pack2_(float lo, float hi) {
    u64 r; asm("mov.b64 %0,{%1,%2};" : "=l"(r) : "f"(lo), "f"(hi)); return r;
}
__device__ __forceinline__ void unpack2_(u64 v, float& lo, float& hi) {
    asm("mov.b64 {%0,%1},%2;" : "=f"(lo), "=f"(hi) : "l"(v));
}

// Scratch (static device arrays — no allocation).
__device__ float g_key[BB * NN * DD];                 // 2 MB
__device__ float g_query[BB * MM * DD];               // 2 MB
__device__ float g_ksum[BB * NN];
__device__ float g_qsum[BB * MM];
__device__ float g_part[SPLITS * NCOMP * BM];         // ~35.7 MB [s][comp][gq]

// ---------------------------------------------------------------------------
// Stage 1: MLP embed (R9-exact: the measured optimum). 2 threads/point,
// 32 output dims each. 128-thread blocks, JCHUNK=128 -> 256 blocks.
// ---------------------------------------------------------------------------
__global__ __launch_bounds__(QBLK) void embed_kernel(
    const float* __restrict__ coords_f, const float* __restrict__ coords_t,
    const float* __restrict__ Wk1, const float* __restrict__ bk1,
    const float* __restrict__ Wk2, const float* __restrict__ bk2,
    const float* __restrict__ Wq1, const float* __restrict__ bq1,
    const float* __restrict__ Wq2, const float* __restrict__ bq2,
    int npts)
{
    __shared__ __align__(16) float W1s[DIN * HH];
    __shared__ float b1s[HH];
    __shared__ float b2s[DD];
    __shared__ __align__(16) float W2h[2][JCHUNK * 32 + 4];

    const int which = blockIdx.y;
    const float* coords = which ? coords_t : coords_f;
    const float* W1 = which ? Wq1 : Wk1;
    const float* b1 = which ? bq1 : bk1;
    const float* W2 = which ? Wq2 : Wk2;
    const float* b2 = which ? bq2 : bk2;
    float* outg = which ? g_query : g_key;
    float* sumg = which ? g_qsum  : g_ksum;

    const int tid = threadIdx.x;
    for (int i = tid; i < DIN * HH; i += QBLK) W1s[i] = W1[i];
    for (int i = tid; i < HH; i += QBLK)       b1s[i] = b1[i];
    for (int i = tid; i < DD; i += QBLK)       b2s[i] = b2[i];

    const int gt   = blockIdx.x * QBLK + tid;
    const int p    = gt >> 1;          // point index (2 threads/point)
    const int half = gt & 1;           // which 32-dim half
    const int d0   = half * 32;

    float c0 = 0.f, c1 = 0.f, c2 = 0.f;
    if (p < npts) {
        c0 = coords[p * 3 + 0];
        c1 = coords[p * 3 + 1];
        c2 = coords[p * 3 + 2];
    }

    float acc[32];
    #pragma unroll
    for (int d = 0; d < 32; d++) acc[d] = 0.f;

    for (int jc = 0; jc < HH; jc += JCHUNK) {
        __syncthreads();
        // stage W2 rows [jc, jc+JCHUNK) split into half-arrays
        {
            const float4* src = (const float4*)(W2 + (size_t)jc * DD);
            for (int idx4 = tid; idx4 < JCHUNK * DD / 4; idx4 += QBLK) {
                int j  = idx4 >> 4;          // row within chunk
                int q4 = idx4 & 15;          // which float4 of the 64-dim row
                int hh = q4 >> 3;            // 0: dims 0-31, 1: dims 32-63
                ((float4*)(W2h[hh] + j * 32))[q4 & 7] = src[idx4];
            }
        }
        __syncthreads();

        const float* Wmine = W2h[half];
        #pragma unroll 2
        for (int j = 0; j < JCHUNK; j++) {
            const int jj = jc + j;
            float h = fmaxf(fmaf(c2, W1s[2 * HH + jj],
                           fmaf(c1, W1s[HH + jj],
                           fmaf(c0, W1s[jj], b1s[jj]))), 0.f);
            const float4* wrow = (const float4*)(Wmine + j * 32);
            #pragma unroll
            for (int q4 = 0; q4 < 8; q4++) {
                float4 w = wrow[q4];
                acc[4 * q4 + 0] = fmaf(h, w.x, acc[4 * q4 + 0]);
                acc[4 * q4 + 1] = fmaf(h, w.y, acc[4 * q4 + 1]);
                acc[4 * q4 + 2] = fmaf(h, w.z, acc[4 * q4 + 2]);
                acc[4 * q4 + 3] = fmaf(h, w.w, acc[4 * q4 + 3]);
            }
        }
    }

    float psum = 0.f;
    if (p < npts) {
        float4* o = (float4*)(outg + (size_t)p * DD + d0);
        #pragma unroll
        for (int q4 = 0; q4 < 8; q4++) {
            float4 r;
            r.x = acc[4 * q4 + 0] + b2s[d0 + 4 * q4 + 0];
            r.y = acc[4 * q4 + 1] + b2s[d0 + 4 * q4 + 1];
            r.z = acc[4 * q4 + 2] + b2s[d0 + 4 * q4 + 2];
            r.w = acc[4 * q4 + 3] + b2s[d0 + 4 * q4 + 3];
            o[q4] = r;
            psum += (r.x + r.y) + (r.z + r.w);
        }
    }
    // combine the 2 sibling lanes' 32-dim partial sums
    psum += __shfl_xor_sync(0xFFFFFFFFu, psum, 1);
    if (p < npts && half == 0) sumg[p] = psum;
}

// ---------------------------------------------------------------------------
// Stage 2: fused L1-cdist (min-sum) + tile-deferred two-pass online softmax
// + PV. Delta vs R9: per-tile logits live in SMEM (lane-owned slots) instead
// of registers, freeing ~16 regs -> occupancy 4 without spills.
// ---------------------------------------------------------------------------
__global__ __launch_bounds__(QBLK, 4) void attn_partial_kernel(
    const float* __restrict__ values)
{
    __shared__ __align__(16) float ks[2][TK * DD];   // 2 x 4 KB
    __shared__ __align__(16) float vs[2][TK * KV];   // 2 x 2 KB
    __shared__ float kss[2][TK];
    __shared__ float lgs[TK][QBLK];                  // 8 KB, lane-owned slots

    const int tid   = threadIdx.x;
    const int b     = blockIdx.y;
    const int m     = blockIdx.x * QBLK + tid;
    const int split = blockIdx.z;
    const int gq    = b * MM + m;

    float q[DD];
    {
        const float4* qp = (const float4*)(g_query + (size_t)gq * DD);
        #pragma unroll
        for (int i = 0; i < DD / 4; i++) {
            float4 v4 = qp[i];
            q[4 * i + 0] = v4.x; q[4 * i + 1] = v4.y;
            q[4 * i + 2] = v4.z; q[4 * i + 3] = v4.w;
        }
    }
    const float qs = g_qsum[gq];

    float mval = -FLT_MAX;
    float ssum = 0.f;
    u64 acc[KV / 2];
    #pragma unroll
    for (int j = 0; j < KV / 2; j++) acc[j] = 0ULL;

    const int    n0      = split * NSPLIT;
    const float* keyBase = g_key  + (size_t)b * NN * DD + (size_t)n0 * DD;
    const float* valBase = values + (size_t)b * NN * KV + (size_t)n0 * KV;
    const float* ksBase  = g_ksum + (size_t)b * NN + n0;

    // preload tile 0: keys 256 float4 (2/thread), values 128 float4 (1/thread)
    ((float4*)ks[0])[tid]        = ((const float4*)keyBase)[tid];
    ((float4*)ks[0])[tid + QBLK] = ((const float4*)keyBase)[tid + QBLK];
    ((float4*)vs[0])[tid]        = ((const float4*)valBase)[tid];
    if (tid < TK)
        kss[0][tid] = ksBase[tid];
    __syncthreads();

    const int NT = NSPLIT / TK;   // 4 tiles
    for (int t = 0; t < NT; t++) {
        const int cur = t & 1;
        if (t + 1 < NT) {
            const float4* nk = (const float4*)(keyBase + (size_t)(t + 1) * TK * DD);
            ((float4*)ks[cur ^ 1])[tid]        = nk[tid];
            ((float4*)ks[cur ^ 1])[tid + QBLK] = nk[tid + QBLK];
            ((float4*)vs[cur ^ 1])[tid] =
                ((const float4*)(valBase + (size_t)(t + 1) * TK * KV))[tid];
            if (tid < TK)
                kss[cur ^ 1][tid] = ksBase[(t + 1) * TK + tid];
        }

        // ---- pass A: L1 via min-sum -> base-2 logits (SMEM) for TK keys ----
        float tm = -FLT_MAX;
        #pragma unroll
        for (int kk = 0; kk < TK; kk++) {
            const float4* kp = (const float4*)(ks[cur] + kk * DD);
            float m0 = 0.f, m1 = 0.f, m2 = 0.f, m3 = 0.f;
            #pragma unroll
            for (int i = 0; i < DD / 4; i++) {
                float4 k4 = kp[i];
                m0 += fminf(k4.x, q[4 * i + 0]);
                m1 += fminf(k4.y, q[4 * i + 1]);
                m2 += fminf(k4.z, q[4 * i + 2]);
                m3 += fminf(k4.w, q[4 * i + 3]);
            }
            float s = fmaf(-2.f, (m0 + m1) + (m2 + m3), kss[cur][kk] + qs);
            float lgv = (NLOG2E_HALF * s) * s;
            lgs[kk][tid] = lgv;          // own slot: no bank conflict, no sync
            tm = fmaxf(tm, lgv);
        }

        // ---- tile-level branchless rescale ----
        float newm = fmaxf(mval, tm);
        float corr = ex2_(mval - newm);     // -FLT_MAX path -> 0
        mval = newm;
        ssum *= corr;
        u64 corrp = pack2_(corr, corr);
        #pragma unroll
        for (int j = 0; j < KV / 2; j++) acc[j] = mul2_(acc[j], corrp);

        // ---- pass B: weights + PV ----
        #pragma unroll
        for (int kk = 0; kk < TK; kk++) {
            float p = ex2_(lgs[kk][tid] - mval);
            ssum += p;
            u64 pp = pack2_(p, p);
            const ulonglong2* vp = (const ulonglong2*)(vs[cur] + kk * KV);
            #pragma unroll
            for (int j = 0; j < KV / 4; j++) {
                ulonglong2 v2 = vp[j];
                acc[2 * j + 0] = fma2_(v2.x, pp, acc[2 * j + 0]);
                acc[2 * j + 1] = fma2_(v2.y, pp, acc[2 * j + 1]);
            }
        }
        __syncthreads();
    }

    // write partial: [split][comp][gq], coalesced across tid
    float* base = g_part + (size_t)split * NCOMP * BM + gq;
    base[0]          = mval;
    base[(size_t)BM] = ssum;
    #pragma unroll
    for (int j = 0; j < KV / 2; j++) {
        float lo, hi;
        unpack2_(acc[j], lo, hi);
        base[(size_t)(2 + 2 * j + 0) * BM] = lo;
        base[(size_t)(2 + 2 * j + 1) * BM] = hi;
    }
}

// ---------------------------------------------------------------------------
// Stage 3: merge with max-reweighting (R9-exact). One thread per
// (query, 2 value dims): 256 blocks x 512 threads; warp lanes span gq.
// ---------------------------------------------------------------------------
__global__ __launch_bounds__(512) void merge_kernel(float* __restrict__ out)
{
    const int lane = threadIdx.x & 31;            // gq within block chunk
    const int duo  = threadIdx.x >> 5;            // which 2 value dims (0..15)
    const int gq   = blockIdx.x * 32 + lane;

    float mx = -FLT_MAX;
    #pragma unroll
    for (int s = 0; s < SPLITS; s++)
        mx = fmaxf(mx, g_part[(size_t)s * NCOMP * BM + gq]);

    float tot = 0.f;
    float a0 = 0.f, a1 = 0.f;
    #pragma unroll
    for (int s = 0; s < SPLITS; s++) {
        const float* base = g_part + (size_t)s * NCOMP * BM + gq;
        float w = ex2_(base[0] - mx);
        tot += base[(size_t)BM] * w;
        const float* ab = base + (size_t)(2 + 2 * duo) * BM;
        a0 += ab[0]          * w;
        a1 += ab[(size_t)BM] * w;
    }

    float inv = 1.f / tot;   // tot >= 1: the argmax split contributes >= 1
    float2 r = make_float2(a0 * inv, a1 * inv);
    *(float2*)(out + (size_t)gq * KV + 2 * duo) = r;
}

// ---------------------------------------------------------------------------
extern "C" void kernel_launch(void* const* d_in, const int* in_sizes, int n_in,
                              void* d_out, int out_size)
{
    const float* coords_f = (const float*)d_in[0];
    const float* values_f = (const float*)d_in[1];
    const float* coords_t = (const float*)d_in[2];
    const float* Wk1 = (const float*)d_in[3];
    const float* bk1 = (const float*)d_in[4];
    const float* Wk2 = (const float*)d_in[5];
    const float* bk2 = (const float*)d_in[6];
    const float* Wq1 = (const float*)d_in[7];
    const float* bq1 = (const float*)d_in[8];
    const float* Wq2 = (const float*)d_in[9];
    const float* bq2 = (const float*)d_in[10];
    float* out = (float*)d_out;

    {
        int npts = BB * NN;                       // 8192
        dim3 grid((npts * 2) / QBLK, 2);          // (128, 2) = 256 blocks
        embed_kernel<<<grid, QBLK>>>(coords_f, coords_t,
                                     Wk1, bk1, Wk2, bk2,
                                     Wq1, bq1, Wq2, bq2, npts);
    }

    {
        dim3 grid(MM / QBLK, BB, SPLITS);         // (16, 4, 32) = 2048 blocks
        attn_partial_kernel<<<grid, QBLK>>>(values_f);
    }

    merge_kernel<<<BM / 32, 512>>>(out);
}

// round 16
// speedup vs baseline: 1.2257x; 1.2257x over previous
#include <cuda_runtime.h>
#include <float.h>

#define BB 4
#define NN 2048
#define MM 2048
#define DIN 3
#define HH 256
#define DD 64
#define KV 32
#define SPLITS 32
#define NSPLIT (NN / SPLITS)   /* 64 keys per split */
#define TK 16                  /* keys per shared tile */
#define QBLK 128               /* attn threads / queries per block */
#define EBLK 256               /* embed threads per block */
#define BM (BB * MM)           /* 8192 queries total */
#define NCOMP (2 + KV)         /* 34 partial components: mval, ssum, acc[32] */
#define JCHUNK 128             /* W2 rows staged per chunk */

typedef unsigned long long u64;
#define NLOG2E_HALF (-0.7213475204444817f)   /* -0.5 * log2(e) */

__device__ __forceinline__ u64 mul2_(u64 a, u64 b) {
    u64 r; asm("mul.rn.f32x2 %0,%1,%2;" : "=l"(r) : "l"(a), "l"(b)); return r;
}
__device__ __forceinline__ u64 fma2_(u64 a, u64 b, u64 c) {
    u64 r; asm("fma.rn.f32x2 %0,%1,%2,%3;" : "=l"(r) : "l"(a), "l"(b), "l"(c)); return r;
}
__device__ __forceinline__ float ex2_(float x) {
    float r; asm("ex2.approx.f32 %0,%1;" : "=f"(r) : "f"(x)); return r;
}
__device__ __forceinline__ u64 pack2_(float lo, float hi) {
    u64 r; asm("mov.b64 %0,{%1,%2};" : "=l"(r) : "f"(lo), "f"(hi)); return r;
}
__device__ __forceinline__ void unpack2_(u64 v, float& lo, float& hi) {
    asm("mov.b64 {%0,%1},%2;" : "=f"(lo), "=f"(hi) : "l"(v));
}

// Scratch (static device arrays — no allocation).
__device__ float g_key[BB * NN * DD];                 // 2 MB
__device__ float g_query[BB * MM * DD];               // 2 MB
__device__ float g_ksum[BB * NN];
__device__ float g_qsum[BB * MM];
__device__ float g_part[SPLITS * NCOMP * BM];         // ~35.7 MB [s][comp][gq]

// ---------------------------------------------------------------------------
// Stage 1: MLP embed. Same per-thread code as the 31.5us R9 version
// (2 threads/point, 32 output dims each, skewed W2 half-arrays), but
// 256-thread blocks -> grid (64,2) = 128 blocks: every SM runs ONE block of
// 8 concurrent warps instead of serializing two 4-warp blocks.
// ---------------------------------------------------------------------------
__global__ __launch_bounds__(EBLK) void embed_kernel(
    const float* __restrict__ coords_f, const float* __restrict__ coords_t,
    const float* __restrict__ Wk1, const float* __restrict__ bk1,
    const float* __restrict__ Wk2, const float* __restrict__ bk2,
    const float* __restrict__ Wq1, const float* __restrict__ bq1,
    const float* __restrict__ Wq2, const float* __restrict__ bq2,
    int npts)
{
    __shared__ __align__(16) float W1s[DIN * HH];
    __shared__ float b1s[HH];
    __shared__ float b2s[DD];
    __shared__ __align__(16) float W2h[2][JCHUNK * 32 + 4];

    const int which = blockIdx.y;
    const float* coords = which ? coords_t : coords_f;
    const float* W1 = which ? Wq1 : Wk1;
    const float* b1 = which ? bq1 : bk1;
    const float* W2 = which ? Wq2 : Wk2;
    const float* b2 = which ? bq2 : bk2;
    float* outg = which ? g_query : g_key;
    float* sumg = which ? g_qsum  : g_ksum;

    const int tid = threadIdx.x;
    for (int i = tid; i < DIN * HH; i += EBLK) W1s[i] = W1[i];
    for (int i = tid; i < HH; i += EBLK)       b1s[i] = b1[i];
    for (int i = tid; i < DD; i += EBLK)       b2s[i] = b2[i];

    const int gt   = blockIdx.x * EBLK + tid;
    const int p    = gt >> 1;          // point index (2 threads/point)
    const int half = gt & 1;           // which 32-dim half
    const int d0   = half * 32;

    float c0 = 0.f, c1 = 0.f, c2 = 0.f;
    if (p < npts) {
        c0 = coords[p * 3 + 0];
        c1 = coords[p * 3 + 1];
        c2 = coords[p * 3 + 2];
    }

    float acc[32];
    #pragma unroll
    for (int d = 0; d < 32; d++) acc[d] = 0.f;

    for (int jc = 0; jc < HH; jc += JCHUNK) {
        __syncthreads();
        // stage W2 rows [jc, jc+JCHUNK) split into half-arrays
        {
            const float4* src = (const float4*)(W2 + (size_t)jc * DD);
            for (int idx4 = tid; idx4 < JCHUNK * DD / 4; idx4 += EBLK) {
                int j  = idx4 >> 4;          // row within chunk
                int q4 = idx4 & 15;          // which float4 of the 64-dim row
                int hh = q4 >> 3;            // 0: dims 0-31, 1: dims 32-63
                ((float4*)(W2h[hh] + j * 32))[q4 & 7] = src[idx4];
            }
        }
        __syncthreads();

        const float* Wmine = W2h[half];
        #pragma unroll 2
        for (int j = 0; j < JCHUNK; j++) {
            const int jj = jc + j;
            float h = fmaxf(fmaf(c2, W1s[2 * HH + jj],
                           fmaf(c1, W1s[HH + jj],
                           fmaf(c0, W1s[jj], b1s[jj]))), 0.f);
            const float4* wrow = (const float4*)(Wmine + j * 32);
            #pragma unroll
            for (int q4 = 0; q4 < 8; q4++) {
                float4 w = wrow[q4];
                acc[4 * q4 + 0] = fmaf(h, w.x, acc[4 * q4 + 0]);
                acc[4 * q4 + 1] = fmaf(h, w.y, acc[4 * q4 + 1]);
                acc[4 * q4 + 2] = fmaf(h, w.z, acc[4 * q4 + 2]);
                acc[4 * q4 + 3] = fmaf(h, w.w, acc[4 * q4 + 3]);
            }
        }
    }

    float psum = 0.f;
    if (p < npts) {
        float4* o = (float4*)(outg + (size_t)p * DD + d0);
        #pragma unroll
        for (int q4 = 0; q4 < 8; q4++) {
            float4 r;
            r.x = acc[4 * q4 + 0] + b2s[d0 + 4 * q4 + 0];
            r.y = acc[4 * q4 + 1] + b2s[d0 + 4 * q4 + 1];
            r.z = acc[4 * q4 + 2] + b2s[d0 + 4 * q4 + 2];
            r.w = acc[4 * q4 + 3] + b2s[d0 + 4 * q4 + 3];
            o[q4] = r;
            psum += (r.x + r.y) + (r.z + r.w);
        }
    }
    // combine the 2 sibling lanes' 32-dim partial sums
    psum += __shfl_xor_sync(0xFFFFFFFFu, psum, 1);
    if (p < npts && half == 0) sumg[p] = psum;
}

// ---------------------------------------------------------------------------
// Stage 2: fused L1-cdist (min-sum) + tile-deferred two-pass online softmax
// + PV. R9-exact: TK=16, plain fminf/+= inner loop, occ 3, no spills.
// ---------------------------------------------------------------------------
__global__ __launch_bounds__(QBLK, 3) void attn_partial_kernel(
    const float* __restrict__ values)
{
    __shared__ __align__(16) float ks[2][TK * DD];   // 2 x 4 KB
    __shared__ __align__(16) float vs[2][TK * KV];   // 2 x 2 KB
    __shared__ float kss[2][TK];

    const int tid   = threadIdx.x;
    const int b     = blockIdx.y;
    const int m     = blockIdx.x * QBLK + tid;
    const int split = blockIdx.z;
    const int gq    = b * MM + m;

    float q[DD];
    {
        const float4* qp = (const float4*)(g_query + (size_t)gq * DD);
        #pragma unroll
        for (int i = 0; i < DD / 4; i++) {
            float4 v4 = qp[i];
            q[4 * i + 0] = v4.x; q[4 * i + 1] = v4.y;
            q[4 * i + 2] = v4.z; q[4 * i + 3] = v4.w;
        }
    }
    const float qs = g_qsum[gq];

    float mval = -FLT_MAX;
    float ssum = 0.f;
    u64 acc[KV / 2];
    #pragma unroll
    for (int j = 0; j < KV / 2; j++) acc[j] = 0ULL;

    const int    n0      = split * NSPLIT;
    const float* keyBase = g_key  + (size_t)b * NN * DD + (size_t)n0 * DD;
    const float* valBase = values + (size_t)b * NN * KV + (size_t)n0 * KV;
    const float* ksBase  = g_ksum + (size_t)b * NN + n0;

    // preload tile 0: keys 256 float4 (2/thread), values 128 float4 (1/thread)
    ((float4*)ks[0])[tid]        = ((const float4*)keyBase)[tid];
    ((float4*)ks[0])[tid + QBLK] = ((const float4*)keyBase)[tid + QBLK];
    ((float4*)vs[0])[tid]        = ((const float4*)valBase)[tid];
    if (tid < TK)
        kss[0][tid] = ksBase[tid];
    __syncthreads();

    const int NT = NSPLIT / TK;   // 4 tiles
    for (int t = 0; t < NT; t++) {
        const int cur = t & 1;
        if (t + 1 < NT) {
            const float4* nk = (const float4*)(keyBase + (size_t)(t + 1) * TK * DD);
            ((float4*)ks[cur ^ 1])[tid]        = nk[tid];
            ((float4*)ks[cur ^ 1])[tid + QBLK] = nk[tid + QBLK];
            ((float4*)vs[cur ^ 1])[tid] =
                ((const float4*)(valBase + (size_t)(t + 1) * TK * KV))[tid];
            if (tid < TK)
                kss[cur ^ 1][tid] = ksBase[(t + 1) * TK + tid];
        }

        // ---- pass A: L1 via min-sum -> base-2 logits for TK keys ----
        float lg[TK];
        float tm = -FLT_MAX;
        #pragma unroll
        for (int kk = 0; kk < TK; kk++) {
            const float4* kp = (const float4*)(ks[cur] + kk * DD);
            float m0 = 0.f, m1 = 0.f, m2 = 0.f, m3 = 0.f;
            #pragma unroll
            for (int i = 0; i < DD / 4; i++) {
                float4 k4 = kp[i];
                m0 += fminf(k4.x, q[4 * i + 0]);
                m1 += fminf(k4.y, q[4 * i + 1]);
                m2 += fminf(k4.z, q[4 * i + 2]);
                m3 += fminf(k4.w, q[4 * i + 3]);
            }
            float s = fmaf(-2.f, (m0 + m1) + (m2 + m3), kss[cur][kk] + qs);
            float lgv = (NLOG2E_HALF * s) * s;
            lg[kk] = lgv;
            tm = fmaxf(tm, lgv);
        }

        // ---- tile-level branchless rescale ----
        float newm = fmaxf(mval, tm);
        float corr = ex2_(mval - newm);     // -FLT_MAX path -> 0
        mval = newm;
        ssum *= corr;
        u64 corrp = pack2_(corr, corr);
        #pragma unroll
        for (int j = 0; j < KV / 2; j++) acc[j] = mul2_(acc[j], corrp);

        // ---- pass B: weights + PV ----
        #pragma unroll
        for (int kk = 0; kk < TK; kk++) {
            float p = ex2_(lg[kk] - mval);
            ssum += p;
            u64 pp = pack2_(p, p);
            const ulonglong2* vp = (const ulonglong2*)(vs[cur] + kk * KV);
            #pragma unroll
            for (int j = 0; j < KV / 4; j++) {
                ulonglong2 v2 = vp[j];
                acc[2 * j + 0] = fma2_(v2.x, pp, acc[2 * j + 0]);
                acc[2 * j + 1] = fma2_(v2.y, pp, acc[2 * j + 1]);
            }
        }
        __syncthreads();
    }

    // write partial: [split][comp][gq], coalesced across tid
    float* base = g_part + (size_t)split * NCOMP * BM + gq;
    base[0]          = mval;
    base[(size_t)BM] = ssum;
    #pragma unroll
    for (int j = 0; j < KV / 2; j++) {
        float lo, hi;
        unpack2_(acc[j], lo, hi);
        base[(size_t)(2 + 2 * j + 0) * BM] = lo;
        base[(size_t)(2 + 2 * j + 1) * BM] = hi;
    }
}

// ---------------------------------------------------------------------------
// Stage 3: merge with max-reweighting (R9-exact). One thread per
// (query, 2 value dims): 256 blocks x 512 threads; warp lanes span gq.
// ---------------------------------------------------------------------------
__global__ __launch_bounds__(512) void merge_kernel(float* __restrict__ out)
{
    const int lane = threadIdx.x & 31;            // gq within block chunk
    const int duo  = threadIdx.x >> 5;            // which 2 value dims (0..15)
    const int gq   = blockIdx.x * 32 + lane;

    float mx = -FLT_MAX;
    #pragma unroll
    for (int s = 0; s < SPLITS; s++)
        mx = fmaxf(mx, g_part[(size_t)s * NCOMP * BM + gq]);

    float tot = 0.f;
    float a0 = 0.f, a1 = 0.f;
    #pragma unroll
    for (int s = 0; s < SPLITS; s++) {
        const float* base = g_part + (size_t)s * NCOMP * BM + gq;
        float w = ex2_(base[0] - mx);
        tot += base[(size_t)BM] * w;
        const float* ab = base + (size_t)(2 + 2 * duo) * BM;
        a0 += ab[0]          * w;
        a1 += ab[(size_t)BM] * w;
    }

    float inv = 1.f / tot;   // tot >= 1: the argmax split contributes >= 1
    float2 r = make_float2(a0 * inv, a1 * inv);
    *(float2*)(out + (size_t)gq * KV + 2 * duo) = r;
}

// ---------------------------------------------------------------------------
extern "C" void kernel_launch(void* const* d_in, const int* in_sizes, int n_in,
                              void* d_out, int out_size)
{
    const float* coords_f = (const float*)d_in[0];
    const float* values_f = (const float*)d_in[1];
    const float* coords_t = (const float*)d_in[2];
    const float* Wk1 = (const float*)d_in[3];
    const float* bk1 = (const float*)d_in[4];
    const float* Wk2 = (const float*)d_in[5];
    const float* bk2 = (const float*)d_in[6];
    const float* Wq1 = (const float*)d_in[7];
    const float* bq1 = (const float*)d_in[8];
    const float* Wq2 = (const float*)d_in[9];
    const float* bq2 = (const float*)d_in[10];
    float* out = (float*)d_out;

    {
        int npts = BB * NN;                       // 8192
        dim3 grid((npts * 2) / EBLK, 2);          // (64, 2) = 128 blocks
        embed_kernel<<<grid, EBLK>>>(coords_f, coords_t,
                                     Wk1, bk1, Wk2, bk2,
                                     Wq1, bq1, Wq2, bq2, npts);
    }

    {
        dim3 grid(MM / QBLK, BB, SPLITS);         // (16, 4, 32) = 2048 blocks
        attn_partial_kernel<<<grid, QBLK>>>(values_f);
    }

    merge_kernel<<<BM / 32, 512>>>(out);
}

// round 17
// speedup vs baseline: 1.2293x; 1.0030x over previous
#include <cuda_runtime.h>
#include <float.h>

#define BB 4
#define NN 2048
#define MM 2048
#define DIN 3
#define HH 256
#define DD 64
#define KV 32
#define SPLITS 32
#define NSPLIT (NN / SPLITS)   /* 64 keys per split */
#define TK 16                  /* keys per shared tile */
#define QBLK 128               /* attn threads / queries per block */
#define EBLK 256               /* embed threads per block */
#define BM (BB * MM)           /* 8192 queries total */
#define NCOMP (2 + KV)         /* 34 partial components: mval, ssum, acc[32] */
#define JCHUNK 128             /* W2 rows staged per chunk */

typedef unsigned long long u64;
#define NLOG2E_HALF (-0.7213475204444817f)   /* -0.5 * log2(e) */

__device__ __forceinline__ u64 mul2_(u64 a, u64 b) {
    u64 r; asm("mul.rn.f32x2 %0,%1,%2;" : "=l"(r) : "l"(a), "l"(b)); return r;
}
__device__ __forceinline__ u64 fma2_(u64 a, u64 b, u64 c) {
    u64 r; asm("fma.rn.f32x2 %0,%1,%2,%3;" : "=l"(r) : "l"(a), "l"(b), "l"(c)); return r;
}
__device__ __forceinline__ float ex2_(float x) {
    float r; asm("ex2.approx.f32 %0,%1;" : "=f"(r) : "f"(x)); return r;
}
__device__ __forceinline__ u64 pack2_(float lo, float hi) {
    u64 r; asm("mov.b64 %0,{%1,%2};" : "=l"(r) : "f"(lo), "f"(hi)); return r;
}
__device__ __forceinline__ void unpack2_(u64 v, float& lo, float& hi) {
    asm("mov.b64 {%0,%1},%2;" : "=f"(lo), "=f"(hi) : "l"(v));
}

// Scratch (static device arrays — no allocation).
__device__ float g_key[BB * NN * DD];                 // 2 MB
__device__ float g_query[BB * MM * DD];               // 2 MB
__device__ float g_ksum[BB * NN];
__device__ float g_qsum[BB * MM];
__device__ float g_part[SPLITS * NCOMP * BM];         // ~35.7 MB [s][comp][gq]

// ---------------------------------------------------------------------------
// Stage 1: MLP embed (R15-exact: measured best, 29.6us). 2 threads/point,
// 32 output dims each; 256-thread blocks -> grid (64,2) = 128 blocks, one
// block per SM in a single wave.
// ---------------------------------------------------------------------------
__global__ __launch_bounds__(EBLK) void embed_kernel(
    const float* __restrict__ coords_f, const float* __restrict__ coords_t,
    const float* __restrict__ Wk1, const float* __restrict__ bk1,
    const float* __restrict__ Wk2, const float* __restrict__ bk2,
    const float* __restrict__ Wq1, const float* __restrict__ bq1,
    const float* __restrict__ Wq2, const float* __restrict__ bq2,
    int npts)
{
    __shared__ __align__(16) float W1s[DIN * HH];
    __shared__ float b1s[HH];
    __shared__ float b2s[DD];
    __shared__ __align__(16) float W2h[2][JCHUNK * 32 + 4];

    const int which = blockIdx.y;
    const float* coords = which ? coords_t : coords_f;
    const float* W1 = which ? Wq1 : Wk1;
    const float* b1 = which ? bq1 : bk1;
    const float* W2 = which ? Wq2 : Wk2;
    const float* b2 = which ? bq2 : bk2;
    float* outg = which ? g_query : g_key;
    float* sumg = which ? g_qsum  : g_ksum;

    const int tid = threadIdx.x;
    for (int i = tid; i < DIN * HH; i += EBLK) W1s[i] = W1[i];
    for (int i = tid; i < HH; i += EBLK)       b1s[i] = b1[i];
    for (int i = tid; i < DD; i += EBLK)       b2s[i] = b2[i];

    const int gt   = blockIdx.x * EBLK + tid;
    const int p    = gt >> 1;          // point index (2 threads/point)
    const int half = gt & 1;           // which 32-dim half
    const int d0   = half * 32;

    float c0 = 0.f, c1 = 0.f, c2 = 0.f;
    if (p < npts) {
        c0 = coords[p * 3 + 0];
        c1 = coords[p * 3 + 1];
        c2 = coords[p * 3 + 2];
    }

    float acc[32];
    #pragma unroll
    for (int d = 0; d < 32; d++) acc[d] = 0.f;

    for (int jc = 0; jc < HH; jc += JCHUNK) {
        __syncthreads();
        // stage W2 rows [jc, jc+JCHUNK) split into half-arrays
        {
            const float4* src = (const float4*)(W2 + (size_t)jc * DD);
            for (int idx4 = tid; idx4 < JCHUNK * DD / 4; idx4 += EBLK) {
                int j  = idx4 >> 4;          // row within chunk
                int q4 = idx4 & 15;          // which float4 of the 64-dim row
                int hh = q4 >> 3;            // 0: dims 0-31, 1: dims 32-63
                ((float4*)(W2h[hh] + j * 32))[q4 & 7] = src[idx4];
            }
        }
        __syncthreads();

        const float* Wmine = W2h[half];
        #pragma unroll 2
        for (int j = 0; j < JCHUNK; j++) {
            const int jj = jc + j;
            float h = fmaxf(fmaf(c2, W1s[2 * HH + jj],
                           fmaf(c1, W1s[HH + jj],
                           fmaf(c0, W1s[jj], b1s[jj]))), 0.f);
            const float4* wrow = (const float4*)(Wmine + j * 32);
            #pragma unroll
            for (int q4 = 0; q4 < 8; q4++) {
                float4 w = wrow[q4];
                acc[4 * q4 + 0] = fmaf(h, w.x, acc[4 * q4 + 0]);
                acc[4 * q4 + 1] = fmaf(h, w.y, acc[4 * q4 + 1]);
                acc[4 * q4 + 2] = fmaf(h, w.z, acc[4 * q4 + 2]);
                acc[4 * q4 + 3] = fmaf(h, w.w, acc[4 * q4 + 3]);
            }
        }
    }

    float psum = 0.f;
    if (p < npts) {
        float4* o = (float4*)(outg + (size_t)p * DD + d0);
        #pragma unroll
        for (int q4 = 0; q4 < 8; q4++) {
            float4 r;
            r.x = acc[4 * q4 + 0] + b2s[d0 + 4 * q4 + 0];
            r.y = acc[4 * q4 + 1] + b2s[d0 + 4 * q4 + 1];
            r.z = acc[4 * q4 + 2] + b2s[d0 + 4 * q4 + 2];
            r.w = acc[4 * q4 + 3] + b2s[d0 + 4 * q4 + 3];
            o[q4] = r;
            psum += (r.x + r.y) + (r.z + r.w);
        }
    }
    // combine the 2 sibling lanes' 32-dim partial sums
    psum += __shfl_xor_sync(0xFFFFFFFFu, psum, 1);
    if (p < npts && half == 0) sumg[p] = psum;
}

// ---------------------------------------------------------------------------
// Stage 2: fused L1-cdist (min-sum) + tile-deferred two-pass online softmax
// + PV. R9-exact: TK=16, plain fminf/+= inner loop, occ 3, no spills.
// ---------------------------------------------------------------------------
__global__ __launch_bounds__(QBLK, 3) void attn_partial_kernel(
    const float* __restrict__ values)
{
    __shared__ __align__(16) float ks[2][TK * DD];   // 2 x 4 KB
    __shared__ __align__(16) float vs[2][TK * KV];   // 2 x 2 KB
    __shared__ float kss[2][TK];

    const int tid   = threadIdx.x;
    const int b     = blockIdx.y;
    const int m     = blockIdx.x * QBLK + tid;
    const int split = blockIdx.z;
    const int gq    = b * MM + m;

    float q[DD];
    {
        const float4* qp = (const float4*)(g_query + (size_t)gq * DD);
        #pragma unroll
        for (int i = 0; i < DD / 4; i++) {
            float4 v4 = qp[i];
            q[4 * i + 0] = v4.x; q[4 * i + 1] = v4.y;
            q[4 * i + 2] = v4.z; q[4 * i + 3] = v4.w;
        }
    }
    const float qs = g_qsum[gq];

    float mval = -FLT_MAX;
    float ssum = 0.f;
    u64 acc[KV / 2];
    #pragma unroll
    for (int j = 0; j < KV / 2; j++) acc[j] = 0ULL;

    const int    n0      = split * NSPLIT;
    const float* keyBase = g_key  + (size_t)b * NN * DD + (size_t)n0 * DD;
    const float* valBase = values + (size_t)b * NN * KV + (size_t)n0 * KV;
    const float* ksBase  = g_ksum + (size_t)b * NN + n0;

    // preload tile 0: keys 256 float4 (2/thread), values 128 float4 (1/thread)
    ((float4*)ks[0])[tid]        = ((const float4*)keyBase)[tid];
    ((float4*)ks[0])[tid + QBLK] = ((const float4*)keyBase)[tid + QBLK];
    ((float4*)vs[0])[tid]        = ((const float4*)valBase)[tid];
    if (tid < TK)
        kss[0][tid] = ksBase[tid];
    __syncthreads();

    const int NT = NSPLIT / TK;   // 4 tiles
    for (int t = 0; t < NT; t++) {
        const int cur = t & 1;
        if (t + 1 < NT) {
            const float4* nk = (const float4*)(keyBase + (size_t)(t + 1) * TK * DD);
            ((float4*)ks[cur ^ 1])[tid]        = nk[tid];
            ((float4*)ks[cur ^ 1])[tid + QBLK] = nk[tid + QBLK];
            ((float4*)vs[cur ^ 1])[tid] =
                ((const float4*)(valBase + (size_t)(t + 1) * TK * KV))[tid];
            if (tid < TK)
                kss[cur ^ 1][tid] = ksBase[(t + 1) * TK + tid];
        }

        // ---- pass A: L1 via min-sum -> base-2 logits for TK keys ----
        float lg[TK];
        float tm = -FLT_MAX;
        #pragma unroll
        for (int kk = 0; kk < TK; kk++) {
            const float4* kp = (const float4*)(ks[cur] + kk * DD);
            float m0 = 0.f, m1 = 0.f, m2 = 0.f, m3 = 0.f;
            #pragma unroll
            for (int i = 0; i < DD / 4; i++) {
                float4 k4 = kp[i];
                m0 += fminf(k4.x, q[4 * i + 0]);
                m1 += fminf(k4.y, q[4 * i + 1]);
                m2 += fminf(k4.z, q[4 * i + 2]);
                m3 += fminf(k4.w, q[4 * i + 3]);
            }
            float s = fmaf(-2.f, (m0 + m1) + (m2 + m3), kss[cur][kk] + qs);
            float lgv = (NLOG2E_HALF * s) * s;
            lg[kk] = lgv;
            tm = fmaxf(tm, lgv);
        }

        // ---- tile-level branchless rescale ----
        float newm = fmaxf(mval, tm);
        float corr = ex2_(mval - newm);     // -FLT_MAX path -> 0
        mval = newm;
        ssum *= corr;
        u64 corrp = pack2_(corr, corr);
        #pragma unroll
        for (int j = 0; j < KV / 2; j++) acc[j] = mul2_(acc[j], corrp);

        // ---- pass B: weights + PV ----
        #pragma unroll
        for (int kk = 0; kk < TK; kk++) {
            float p = ex2_(lg[kk] - mval);
            ssum += p;
            u64 pp = pack2_(p, p);
            const ulonglong2* vp = (const ulonglong2*)(vs[cur] + kk * KV);
            #pragma unroll
            for (int j = 0; j < KV / 4; j++) {
                ulonglong2 v2 = vp[j];
                acc[2 * j + 0] = fma2_(v2.x, pp, acc[2 * j + 0]);
                acc[2 * j + 1] = fma2_(v2.y, pp, acc[2 * j + 1]);
            }
        }
        __syncthreads();
    }

    // write partial: [split][comp][gq], coalesced across tid
    float* base = g_part + (size_t)split * NCOMP * BM + gq;
    base[0]          = mval;
    base[(size_t)BM] = ssum;
    #pragma unroll
    for (int j = 0; j < KV / 2; j++) {
        float lo, hi;
        unpack2_(acc[j], lo, hi);
        base[(size_t)(2 + 2 * j + 0) * BM] = lo;
        base[(size_t)(2 + 2 * j + 1) * BM] = hi;
    }
}

// ---------------------------------------------------------------------------
// Stage 3: merge with max-reweighting. Same per-thread code as before, but
// 128-thread blocks, grid (256, 4) = 1024 blocks (6.9/SM) to remove the
// 2-blocks-per-SM serialization. Warp = 32 consecutive gq x one duo.
// ---------------------------------------------------------------------------
__global__ __launch_bounds__(128) void merge_kernel(float* __restrict__ out)
{
    const int lane = threadIdx.x & 31;                       // gq within chunk
    const int duo  = (threadIdx.x >> 5) + 4 * blockIdx.y;    // 0..15
    const int gq   = blockIdx.x * 32 + lane;

    float mx = -FLT_MAX;
    #pragma unroll
    for (int s = 0; s < SPLITS; s++)
        mx = fmaxf(mx, g_part[(size_t)s * NCOMP * BM + gq]);

    float tot = 0.f;
    float a0 = 0.f, a1 = 0.f;
    #pragma unroll
    for (int s = 0; s < SPLITS; s++) {
        const float* base = g_part + (size_t)s * NCOMP * BM + gq;
        float w = ex2_(base[0] - mx);
        tot += base[(size_t)BM] * w;
        const float* ab = base + (size_t)(2 + 2 * duo) * BM;
        a0 += ab[0]          * w;
        a1 += ab[(size_t)BM] * w;
    }

    float inv = 1.f / tot;   // tot >= 1: the argmax split contributes >= 1
    float2 r = make_float2(a0 * inv, a1 * inv);
    *(float2*)(out + (size_t)gq * KV + 2 * duo) = r;
}

// ---------------------------------------------------------------------------
extern "C" void kernel_launch(void* const* d_in, const int* in_sizes, int n_in,
                              void* d_out, int out_size)
{
    const float* coords_f = (const float*)d_in[0];
    const float* values_f = (const float*)d_in[1];
    const float* coords_t = (const float*)d_in[2];
    const float* Wk1 = (const float*)d_in[3];
    const float* bk1 = (const float*)d_in[4];
    const float* Wk2 = (const float*)d_in[5];
    const float* bk2 = (const float*)d_in[6];
    const float* Wq1 = (const float*)d_in[7];
    const float* bq1 = (const float*)d_in[8];
    const float* Wq2 = (const float*)d_in[9];
    const float* bq2 = (const float*)d_in[10];
    float* out = (float*)d_out;

    {
        int npts = BB * NN;                       // 8192
        dim3 grid((npts * 2) / EBLK, 2);          // (64, 2) = 128 blocks
        embed_kernel<<<grid, EBLK>>>(coords_f, coords_t,
                                     Wk1, bk1, Wk2, bk2,
                                     Wq1, bq1, Wq2, bq2, npts);
    }

    {
        dim3 grid(MM / QBLK, BB, SPLITS);         // (16, 4, 32) = 2048 blocks
        attn_partial_kernel<<<grid, QBLK>>>(values_f);
    }

    {
        dim3 grid(BM / 32, 4);                    // (256, 4) = 1024 blocks
        merge_kernel<<<grid, 128>>>(out);
    }
}